// round 1
// baseline (speedup 1.0000x reference)
#include <cuda_runtime.h>
#include <cstdint>

#define NN 100000
#define NE 20000
#define DF 128
#define GEMM_ROWS 64

// ---------------- scratch (allocation-free: __device__ globals) ----------------
__device__ __align__(16) int   g_dv[NN];
__device__ __align__(16) int   g_de[NE];
__device__ __align__(16) float g_Xs[(size_t)NN * DF];   // 51.2 MB
__device__ __align__(16) float g_Ye[(size_t)NE * DF];   // 10.24 MB

__device__ __forceinline__ void red_add_v4(float* addr, float4 v) {
    asm volatile("red.global.add.v4.f32 [%0], {%1, %2, %3, %4};"
                 :: "l"(addr), "f"(v.x), "f"(v.y), "f"(v.z), "f"(v.w)
                 : "memory");
}

// ---------------- init: zero out, Ye, degree counters ----------------
__global__ void k_init(float4* __restrict__ out4) {
    int i = blockIdx.x * blockDim.x + threadIdx.x;
    const int OUT4 = NN * DF / 4;   // 3.2M
    const int YE4  = NE * DF / 4;   // 640K
    if (i < OUT4) out4[i] = make_float4(0.f, 0.f, 0.f, 0.f);
    if (i < YE4)  ((float4*)g_Ye)[i] = make_float4(0.f, 0.f, 0.f, 0.f);
    if (i < NN)   g_dv[i] = 0;
    if (i < NE)   g_de[i] = 0;
}

// ---------------- degrees ----------------
__global__ void k_degree(const int* __restrict__ v_idx,
                         const int* __restrict__ e_idx, int nnz) {
    int i = blockIdx.x * blockDim.x + threadIdx.x;
    if (i < nnz) {
        atomicAdd(&g_dv[v_idx[i]], 1);
        atomicAdd(&g_de[e_idx[i]], 1);
    }
}

// ---------------- GEMM: Xs = (X @ W + b) * inv_sqrt_dv ----------------
// 256 threads/block, 64 rows/block. W (64KB) + X tile (32KB) in dynamic smem.
// Warp w handles rows [8w, 8w+8); lane l handles cols [4l, 4l+4).
__global__ __launch_bounds__(256, 2) void k_gemm(const float* __restrict__ X,
                                                 const float* __restrict__ W,
                                                 const float* __restrict__ b) {
    extern __shared__ float smem[];
    float* Ws  = smem;              // [DF*DF]
    float* Xsh = smem + DF * DF;    // [GEMM_ROWS*DF]
    int tid  = threadIdx.x;
    int row0 = blockIdx.x * GEMM_ROWS;

    float4*       Ws4 = (float4*)Ws;
    const float4* W4  = (const float4*)W;
    #pragma unroll
    for (int j = 0; j < (DF * DF / 4) / 256; ++j)       // 16 iters
        Ws4[tid + j * 256] = W4[tid + j * 256];

    float4*       Xs4s = (float4*)Xsh;
    const float4* X4   = (const float4*)X;
    #pragma unroll
    for (int j = 0; j < (GEMM_ROWS * DF / 4) / 256; ++j) {  // 8 iters
        int idx  = tid + j * 256;
        int r    = idx >> 5;            // /(DF/4)
        int rowg = row0 + r;
        Xs4s[idx] = (rowg < NN) ? X4[(size_t)rowg * (DF / 4) + (idx & 31)]
                                : make_float4(0.f, 0.f, 0.f, 0.f);
    }
    __syncthreads();

    int warp = tid >> 5, lane = tid & 31;
    int rbase = warp * 8;
    float acc[8][4];
    #pragma unroll
    for (int r = 0; r < 8; ++r)
        acc[r][0] = acc[r][1] = acc[r][2] = acc[r][3] = 0.f;

    #pragma unroll 4
    for (int k = 0; k < DF; ++k) {
        float4 wv = Ws4[k * (DF / 4) + lane];
        #pragma unroll
        for (int r = 0; r < 8; ++r) {
            float xv = Xsh[(rbase + r) * DF + k];
            acc[r][0] = fmaf(xv, wv.x, acc[r][0]);
            acc[r][1] = fmaf(xv, wv.y, acc[r][1]);
            acc[r][2] = fmaf(xv, wv.z, acc[r][2]);
            acc[r][3] = fmaf(xv, wv.w, acc[r][3]);
        }
    }

    float4 bv = ((const float4*)b)[lane];
    #pragma unroll
    for (int r = 0; r < 8; ++r) {
        int rowg = row0 + rbase + r;
        if (rowg < NN) {
            int   dv = g_dv[rowg];
            float s  = dv > 0 ? rsqrtf((float)dv) : 0.f;
            float4 o;
            o.x = (acc[r][0] + bv.x) * s;
            o.y = (acc[r][1] + bv.y) * s;
            o.z = (acc[r][2] + bv.z) * s;
            o.w = (acc[r][3] + bv.w) * s;
            ((float4*)g_Xs)[(size_t)rowg * (DF / 4) + lane] = o;
        }
    }
}

// ---------------- scatter 1: Ye[e] += Xs[v]  (warp per nnz, v4 reds) ----------------
__global__ __launch_bounds__(256) void k_scatter1(const int* __restrict__ v_idx,
                                                  const int* __restrict__ e_idx,
                                                  int nnz) {
    int w    = (int)((blockIdx.x * (unsigned)blockDim.x + threadIdx.x) >> 5);
    int lane = threadIdx.x & 31;
    if (w >= nnz) return;
    int v = __ldg(&v_idx[w]);
    int e = __ldg(&e_idx[w]);
    float4 val = *(const float4*)&g_Xs[(size_t)v * DF + lane * 4];
    red_add_v4(&g_Ye[(size_t)e * DF + lane * 4], val);
}

// ---------------- scatter 2: out[v] += Ye[e] * inv_de[e] ----------------
__global__ __launch_bounds__(256) void k_scatter2(const int* __restrict__ v_idx,
                                                  const int* __restrict__ e_idx,
                                                  int nnz, float* __restrict__ out) {
    int w    = (int)((blockIdx.x * (unsigned)blockDim.x + threadIdx.x) >> 5);
    int lane = threadIdx.x & 31;
    if (w >= nnz) return;
    int v  = __ldg(&v_idx[w]);
    int e  = __ldg(&e_idx[w]);
    int de = g_de[e];
    float sc = de > 0 ? 1.0f / (float)de : 0.f;
    float4 y = *(const float4*)&g_Ye[(size_t)e * DF + lane * 4];
    y.x *= sc; y.y *= sc; y.z *= sc; y.w *= sc;
    red_add_v4(&out[(size_t)v * DF + lane * 4], y);
}

// ---------------- finalize: out = relu(out * inv_sqrt_dv) ----------------
__global__ void k_final(float4* __restrict__ out4) {
    int i = blockIdx.x * blockDim.x + threadIdx.x;
    if (i >= NN * DF / 4) return;
    int   row = i >> 5;                // /(DF/4)
    int   dv  = g_dv[row];
    float s   = dv > 0 ? rsqrtf((float)dv) : 0.f;
    float4 o = out4[i];
    o.x = fmaxf(o.x * s, 0.f);
    o.y = fmaxf(o.y * s, 0.f);
    o.z = fmaxf(o.z * s, 0.f);
    o.w = fmaxf(o.w * s, 0.f);
    out4[i] = o;
}

// ---------------- launch ----------------
extern "C" void kernel_launch(void* const* d_in, const int* in_sizes, int n_in,
                              void* d_out, int out_size) {
    const float* X     = (const float*)d_in[0];
    const float* W     = (const float*)d_in[1];
    const float* b     = (const float*)d_in[2];
    const int*   v_idx = (const int*)d_in[3];
    const int*   e_idx = (const int*)d_in[4];
    float*       out   = (float*)d_out;
    int          nnz   = in_sizes[3];

    const int smem_gemm = (DF * DF + GEMM_ROWS * DF) * (int)sizeof(float);  // 96KB
    cudaFuncSetAttribute(k_gemm, cudaFuncAttributeMaxDynamicSharedMemorySize, smem_gemm);

    k_init<<<(NN * DF / 4 + 255) / 256, 256>>>((float4*)out);
    k_degree<<<(nnz + 255) / 256, 256>>>(v_idx, e_idx, nnz);
    k_gemm<<<(NN + GEMM_ROWS - 1) / GEMM_ROWS, 256, smem_gemm>>>(X, W, b);

    long long threads = (long long)nnz * 32;
    int blocks = (int)((threads + 255) / 256);
    k_scatter1<<<blocks, 256>>>(v_idx, e_idx, nnz);
    k_scatter2<<<blocks, 256>>>(v_idx, e_idx, nnz, out);
    k_final<<<(NN * DF / 4 + 255) / 256, 256>>>((float4*)out);
}

// round 2
// speedup vs baseline: 1.8868x; 1.8868x over previous
#include <cuda_runtime.h>
#include <cstdint>

#define NN  100000
#define NE  20000
#define DF  128
#define NNZ_MAX 1600000
#define NSEG (NE + NN)          // combined segment count: edges first, then vertices
#define GEMM_ROWS 64

// ---------------- scratch (allocation-free: __device__ globals) ----------------
__device__ __align__(16) int   g_cnt[NSEG];          // [0,NE): edge deg, [NE,NSEG): vertex deg
__device__ __align__(16) int   g_off[NSEG];          // exclusive-scan offsets into g_list
__device__ __align__(16) int   g_cur[NSEG];          // fill cursors
__device__ __align__(16) int   g_list[2 * NNZ_MAX];  // edge buckets: vertex ids; vertex buckets: edge ids
__device__ __align__(16) int   g_bsum[192];          // block sums for scan
__device__ __align__(16) float g_Xs[(size_t)NN * DF];   // 51.2 MB: (XW+b)*inv_sqrt_dv
__device__ __align__(16) float g_Ye[(size_t)NE * DF];   // 10.24 MB: edge features (already *inv_de)

// ---------------- zero counters ----------------
__global__ void k_zero() {
    int i = blockIdx.x * blockDim.x + threadIdx.x;
    if (i < NSEG) g_cnt[i] = 0;
}

// ---------------- degrees (combined counts) ----------------
__global__ void k_degree(const int* __restrict__ v_idx,
                         const int* __restrict__ e_idx, int nnz) {
    int i = blockIdx.x * blockDim.x + threadIdx.x;
    if (i < nnz) {
        atomicAdd(&g_cnt[e_idx[i]], 1);
        atomicAdd(&g_cnt[NE + v_idx[i]], 1);
    }
}

// ---------------- exclusive scan (3 kernels, n = NSEG = 120000) ----------------
__global__ void k_scan1(int n) {
    __shared__ int sh[1024];
    int tid = threadIdx.x;
    int i = blockIdx.x * 1024 + tid;
    int v = (i < n) ? g_cnt[i] : 0;
    sh[tid] = v;
    __syncthreads();
    #pragma unroll
    for (int d = 1; d < 1024; d <<= 1) {
        int t = (tid >= d) ? sh[tid - d] : 0;
        __syncthreads();
        sh[tid] += t;
        __syncthreads();
    }
    if (i < n) g_off[i] = sh[tid] - v;           // exclusive within block
    if (tid == 1023) g_bsum[blockIdx.x] = sh[1023];
}

__global__ void k_scan2(int nb) {
    __shared__ int sh[128];
    int tid = threadIdx.x;
    int v = (tid < nb) ? g_bsum[tid] : 0;
    sh[tid] = v;
    __syncthreads();
    #pragma unroll
    for (int d = 1; d < 128; d <<= 1) {
        int t = (tid >= d) ? sh[tid - d] : 0;
        __syncthreads();
        sh[tid] += t;
        __syncthreads();
    }
    if (tid < nb) g_bsum[tid] = sh[tid] - v;     // exclusive block offsets
}

__global__ void k_scan3(int n) {
    int i = blockIdx.x * 1024 + threadIdx.x;
    if (i < n) {
        int o = g_off[i] + g_bsum[blockIdx.x];
        g_off[i] = o;
        g_cur[i] = o;
    }
}

// ---------------- fill combined adjacency list ----------------
__global__ void k_fill(const int* __restrict__ v_idx,
                       const int* __restrict__ e_idx, int nnz) {
    int i = blockIdx.x * blockDim.x + threadIdx.x;
    if (i < nnz) {
        int v = v_idx[i], e = e_idx[i];
        int pe = atomicAdd(&g_cur[e], 1);
        g_list[pe] = v;
        int pv = atomicAdd(&g_cur[NE + v], 1);
        g_list[pv] = e;
    }
}

// ---------------- GEMM: Xs = (X @ W + b) * inv_sqrt_dv ----------------
__global__ __launch_bounds__(256, 2) void k_gemm(const float* __restrict__ X,
                                                 const float* __restrict__ W,
                                                 const float* __restrict__ b) {
    extern __shared__ float smem[];
    float* Ws  = smem;              // [DF*DF]
    float* Xsh = smem + DF * DF;    // [GEMM_ROWS*DF]
    int tid  = threadIdx.x;
    int row0 = blockIdx.x * GEMM_ROWS;

    float4*       Ws4 = (float4*)Ws;
    const float4* W4  = (const float4*)W;
    #pragma unroll
    for (int j = 0; j < (DF * DF / 4) / 256; ++j)
        Ws4[tid + j * 256] = W4[tid + j * 256];

    float4*       Xs4s = (float4*)Xsh;
    const float4* X4   = (const float4*)X;
    #pragma unroll
    for (int j = 0; j < (GEMM_ROWS * DF / 4) / 256; ++j) {
        int idx  = tid + j * 256;
        int r    = idx >> 5;
        int rowg = row0 + r;
        Xs4s[idx] = (rowg < NN) ? X4[(size_t)rowg * (DF / 4) + (idx & 31)]
                                : make_float4(0.f, 0.f, 0.f, 0.f);
    }
    __syncthreads();

    int warp = tid >> 5, lane = tid & 31;
    int rbase = warp * 8;
    float acc[8][4];
    #pragma unroll
    for (int r = 0; r < 8; ++r)
        acc[r][0] = acc[r][1] = acc[r][2] = acc[r][3] = 0.f;

    #pragma unroll 4
    for (int k = 0; k < DF; ++k) {
        float4 wv = Ws4[k * (DF / 4) + lane];
        #pragma unroll
        for (int r = 0; r < 8; ++r) {
            float xv = Xsh[(rbase + r) * DF + k];
            acc[r][0] = fmaf(xv, wv.x, acc[r][0]);
            acc[r][1] = fmaf(xv, wv.y, acc[r][1]);
            acc[r][2] = fmaf(xv, wv.z, acc[r][2]);
            acc[r][3] = fmaf(xv, wv.w, acc[r][3]);
        }
    }

    float4 bv = ((const float4*)b)[lane];
    #pragma unroll
    for (int r = 0; r < 8; ++r) {
        int rowg = row0 + rbase + r;
        if (rowg < NN) {
            int   dv = g_cnt[NE + rowg];
            float s  = dv > 0 ? rsqrtf((float)dv) : 0.f;
            float4 o;
            o.x = (acc[r][0] + bv.x) * s;
            o.y = (acc[r][1] + bv.y) * s;
            o.z = (acc[r][2] + bv.z) * s;
            o.w = (acc[r][3] + bv.w) * s;
            ((float4*)g_Xs)[(size_t)rowg * (DF / 4) + lane] = o;
        }
    }
}

// ---------------- edge gather: Ye[e] = (sum_{v in e} Xs[v]) / de ----------------
__global__ __launch_bounds__(256) void k_edge() {
    int w    = (int)((blockIdx.x * (unsigned)blockDim.x + threadIdx.x) >> 5);
    int lane = threadIdx.x & 31;
    if (w >= NE) return;
    int start = g_off[w];
    int de    = g_cnt[w];
    const float4* Xs4 = (const float4*)g_Xs;

    float4 acc = make_float4(0.f, 0.f, 0.f, 0.f);
    for (int base = 0; base < de; base += 32) {
        int j   = base + lane;
        int idx = (j < de) ? g_list[start + j] : 0;
        int m   = min(32, de - base);
        #pragma unroll 4
        for (int t = 0; t < m; ++t) {
            int v = __shfl_sync(0xffffffffu, idx, t);
            float4 x = __ldg(&Xs4[(size_t)v * (DF / 4) + lane]);
            acc.x += x.x; acc.y += x.y; acc.z += x.z; acc.w += x.w;
        }
    }
    float sc = de > 0 ? 1.0f / (float)de : 0.f;
    acc.x *= sc; acc.y *= sc; acc.z *= sc; acc.w *= sc;
    ((float4*)g_Ye)[(size_t)w * (DF / 4) + lane] = acc;
}

// ---------------- vertex gather + finalize: out[v] = relu(inv_sqrt_dv * sum Ye[e]) ----------------
__global__ __launch_bounds__(256) void k_vert(float* __restrict__ out) {
    int w    = (int)((blockIdx.x * (unsigned)blockDim.x + threadIdx.x) >> 5);
    int lane = threadIdx.x & 31;
    if (w >= NN) return;
    int start = g_off[NE + w];
    int dv    = g_cnt[NE + w];
    const float4* Ye4 = (const float4*)g_Ye;

    float4 acc = make_float4(0.f, 0.f, 0.f, 0.f);
    for (int base = 0; base < dv; base += 32) {
        int j   = base + lane;
        int idx = (j < dv) ? g_list[start + j] : 0;
        int m   = min(32, dv - base);
        #pragma unroll 4
        for (int t = 0; t < m; ++t) {
            int e = __shfl_sync(0xffffffffu, idx, t);
            float4 y = __ldg(&Ye4[(size_t)e * (DF / 4) + lane]);
            acc.x += y.x; acc.y += y.y; acc.z += y.z; acc.w += y.w;
        }
    }
    float s = dv > 0 ? rsqrtf((float)dv) : 0.f;
    float4 o;
    o.x = fmaxf(acc.x * s, 0.f);
    o.y = fmaxf(acc.y * s, 0.f);
    o.z = fmaxf(acc.z * s, 0.f);
    o.w = fmaxf(acc.w * s, 0.f);
    ((float4*)out)[(size_t)w * (DF / 4) + lane] = o;
}

// ---------------- launch ----------------
extern "C" void kernel_launch(void* const* d_in, const int* in_sizes, int n_in,
                              void* d_out, int out_size) {
    const float* X     = (const float*)d_in[0];
    const float* W     = (const float*)d_in[1];
    const float* b     = (const float*)d_in[2];
    const int*   v_idx = (const int*)d_in[3];
    const int*   e_idx = (const int*)d_in[4];
    float*       out   = (float*)d_out;
    int          nnz   = in_sizes[3];

    const int smem_gemm = (DF * DF + GEMM_ROWS * DF) * (int)sizeof(float);  // 96KB
    cudaFuncSetAttribute(k_gemm, cudaFuncAttributeMaxDynamicSharedMemorySize, smem_gemm);

    const int nScanBlocks = (NSEG + 1023) / 1024;   // 118

    k_zero<<<(NSEG + 255) / 256, 256>>>();
    k_degree<<<(nnz + 255) / 256, 256>>>(v_idx, e_idx, nnz);
    k_scan1<<<nScanBlocks, 1024>>>(NSEG);
    k_scan2<<<1, 128>>>(nScanBlocks);
    k_scan3<<<nScanBlocks, 1024>>>(NSEG);
    k_fill<<<(nnz + 255) / 256, 256>>>(v_idx, e_idx, nnz);
    k_gemm<<<(NN + GEMM_ROWS - 1) / GEMM_ROWS, 256, smem_gemm>>>(X, W, b);
    k_edge<<<(NE * 32 + 255) / 256, 256>>>();
    k_vert<<<(NN * 32 + 255) / 256, 256>>>(out);
}

// round 3
// speedup vs baseline: 2.1362x; 1.1322x over previous
#include <cuda_runtime.h>
#include <cuda_fp16.h>
#include <cstdint>

#define NN  100000
#define NE  20000
#define DF  128
#define NNZ_MAX 1600000
#define NSEG (NE + NN)
#define GR 128          // GEMM rows per block
#define GT 512          // GEMM threads per block

// ---------------- scratch (allocation-free: __device__ globals) ----------------
__device__ __align__(16) int    g_cnt[NSEG];          // [0,NE): edge deg, [NE,NSEG): vertex deg
__device__ __align__(16) int    g_off[NSEG];
__device__ __align__(16) int    g_cur[NSEG];
__device__ __align__(16) int    g_list[2 * NNZ_MAX];
__device__ __align__(16) int    g_bsum[192];
__device__ __align__(16) __half g_Xs[(size_t)NN * DF];   // 25.6 MB (fp16)
__device__ __align__(16) __half g_Ye[(size_t)NE * DF];   // 5.1 MB (fp16)

// ---------------- zero counters ----------------
__global__ void k_zero() {
    int i = blockIdx.x * blockDim.x + threadIdx.x;
    if (i < NSEG) g_cnt[i] = 0;
}

// ---------------- degrees ----------------
__global__ void k_degree(const int* __restrict__ v_idx,
                         const int* __restrict__ e_idx, int nnz) {
    int i = blockIdx.x * blockDim.x + threadIdx.x;
    if (i < nnz) {
        atomicAdd(&g_cnt[e_idx[i]], 1);
        atomicAdd(&g_cnt[NE + v_idx[i]], 1);
    }
}

// ---------------- exclusive scan (n = NSEG) ----------------
__global__ void k_scan1(int n) {
    __shared__ int sh[1024];
    int tid = threadIdx.x;
    int i = blockIdx.x * 1024 + tid;
    int v = (i < n) ? g_cnt[i] : 0;
    sh[tid] = v;
    __syncthreads();
    #pragma unroll
    for (int d = 1; d < 1024; d <<= 1) {
        int t = (tid >= d) ? sh[tid - d] : 0;
        __syncthreads();
        sh[tid] += t;
        __syncthreads();
    }
    if (i < n) g_off[i] = sh[tid] - v;
    if (tid == 1023) g_bsum[blockIdx.x] = sh[1023];
}

__global__ void k_scan2(int nb) {
    __shared__ int sh[128];
    int tid = threadIdx.x;
    int v = (tid < nb) ? g_bsum[tid] : 0;
    sh[tid] = v;
    __syncthreads();
    #pragma unroll
    for (int d = 1; d < 128; d <<= 1) {
        int t = (tid >= d) ? sh[tid - d] : 0;
        __syncthreads();
        sh[tid] += t;
        __syncthreads();
    }
    if (tid < nb) g_bsum[tid] = sh[tid] - v;
}

__global__ void k_scan3(int n) {
    int i = blockIdx.x * 1024 + threadIdx.x;
    if (i < n) {
        int o = g_off[i] + g_bsum[blockIdx.x];
        g_off[i] = o;
        g_cur[i] = o;
    }
}

// ---------------- fill combined adjacency list ----------------
__global__ void k_fill(const int* __restrict__ v_idx,
                       const int* __restrict__ e_idx, int nnz) {
    int i = blockIdx.x * blockDim.x + threadIdx.x;
    if (i < nnz) {
        int v = v_idx[i], e = e_idx[i];
        int pe = atomicAdd(&g_cur[e], 1);
        g_list[pe] = v;
        int pv = atomicAdd(&g_cur[NE + v], 1);
        g_list[pv] = e;
    }
}

// ---------------- GEMM: Xs = half((X @ W + b) * inv_sqrt_dv), FFMA2 over K pairs ----------------
// acc[r][c] is f32x2 = (sum over even k, sum over odd k); summed at epilogue.
// Xsh row-major [GR][DF]; Wt transposed [DF cols][DF k] with XOR swizzle on k.
__global__ __launch_bounds__(GT, 1) void k_gemm(const float* __restrict__ X,
                                                const float* __restrict__ W,
                                                const float* __restrict__ b) {
    extern __shared__ float smem[];
    float* Xsh = smem;             // [GR*DF]  64 KB
    float* Wt  = smem + GR * DF;   // [DF*DF]  64 KB
    int tid  = threadIdx.x;
    int row0 = blockIdx.x * GR;

    // X tile, row-major
    const float4* X4   = (const float4*)X;
    float4*       Xsh4 = (float4*)Xsh;
    #pragma unroll
    for (int j = 0; j < (GR * DF / 4) / GT; ++j) {    // 8 iters
        int idx  = tid + j * GT;
        int r    = idx >> 5;
        int rowg = row0 + r;
        Xsh4[idx] = (rowg < NN) ? X4[(size_t)rowg * (DF / 4) + (idx & 31)]
                                : make_float4(0.f, 0.f, 0.f, 0.f);
    }
    // W transposed + swizzled: Wt[c*DF + (k ^ 2*((c>>2)&15))] = W[k][c]
    const float4* W4 = (const float4*)W;
    #pragma unroll
    for (int j = 0; j < (DF * DF / 4) / GT; ++j) {    // 8 iters
        int idx = tid + j * GT;
        int k   = idx >> 5;
        int c4  = idx & 31;
        float4 wv = W4[idx];
        int kk = k ^ (2 * (c4 & 15));
        Wt[(4 * c4 + 0) * DF + kk] = wv.x;
        Wt[(4 * c4 + 1) * DF + kk] = wv.y;
        Wt[(4 * c4 + 2) * DF + kk] = wv.z;
        Wt[(4 * c4 + 3) * DF + kk] = wv.w;
    }
    __syncthreads();

    int warp  = tid >> 5, lane = tid & 31;
    int rbase = warp * 8;                 // 16 warps * 8 rows = 128
    int swl   = 2 * (lane & 15);

    unsigned long long acc[8][4];
    #pragma unroll
    for (int r = 0; r < 8; ++r)
        #pragma unroll
        for (int c = 0; c < 4; ++c) acc[r][c] = 0ull;

    const float* xrow = Xsh + rbase * DF;
    const float* wcol = Wt + (4 * lane) * DF;

    #pragma unroll 2
    for (int k2 = 0; k2 < DF / 2; ++k2) {
        int xo = 2 * k2;
        int wo = (2 * k2) ^ swl;
        unsigned long long xp[8], wp[4];
        #pragma unroll
        for (int r = 0; r < 8; ++r)
            xp[r] = *(const unsigned long long*)&xrow[r * DF + xo];
        #pragma unroll
        for (int c = 0; c < 4; ++c)
            wp[c] = *(const unsigned long long*)&wcol[c * DF + wo];
        #pragma unroll
        for (int r = 0; r < 8; ++r)
            #pragma unroll
            for (int c = 0; c < 4; ++c)
                asm("fma.rn.f32x2 %0, %1, %2, %0;"
                    : "+l"(acc[r][c]) : "l"(xp[r]), "l"(wp[c]));
    }

    float4 bv = ((const float4*)b)[lane];
    #pragma unroll
    for (int r = 0; r < 8; ++r) {
        int rowg = row0 + rbase + r;
        if (rowg < NN) {
            int   dv = g_cnt[NE + rowg];
            float s  = dv > 0 ? rsqrtf((float)dv) : 0.f;
            float f[4];
            #pragma unroll
            for (int c = 0; c < 4; ++c) {
                float lo = __uint_as_float((unsigned)acc[r][c]);
                float hi = __uint_as_float((unsigned)(acc[r][c] >> 32));
                float bb = (c == 0) ? bv.x : (c == 1) ? bv.y : (c == 2) ? bv.z : bv.w;
                f[c] = (lo + hi + bb) * s;
            }
            __half2 h01 = __floats2half2_rn(f[0], f[1]);
            __half2 h23 = __floats2half2_rn(f[2], f[3]);
            uint2 o;
            o.x = *(unsigned*)&h01;
            o.y = *(unsigned*)&h23;
            *(uint2*)&g_Xs[(size_t)rowg * DF + 4 * lane] = o;
        }
    }
}

// ---------------- edge gather: Ye[e] = half((sum Xs[v]) / de) ----------------
__global__ __launch_bounds__(256) void k_edge() {
    int w    = (int)((blockIdx.x * 256u + threadIdx.x) >> 5);
    int lane = threadIdx.x & 31;
    if (w >= NE) return;
    int start = g_off[w];
    int de    = g_cnt[w];

    float a0 = 0.f, a1 = 0.f, a2 = 0.f, a3 = 0.f;
    for (int base = 0; base < de; base += 32) {
        int j   = base + lane;
        int idx = (j < de) ? g_list[start + j] : 0;
        int m   = min(32, de - base);
        #pragma unroll 4
        for (int t = 0; t < m; ++t) {
            int v = __shfl_sync(0xffffffffu, idx, t);
            uint2 u = __ldg((const uint2*)&g_Xs[(size_t)v * DF + 4 * lane]);
            float2 p = __half22float2(*(__half2*)&u.x);
            float2 q = __half22float2(*(__half2*)&u.y);
            a0 += p.x; a1 += p.y; a2 += q.x; a3 += q.y;
        }
    }
    float sc = de > 0 ? 1.0f / (float)de : 0.f;
    __half2 h01 = __floats2half2_rn(a0 * sc, a1 * sc);
    __half2 h23 = __floats2half2_rn(a2 * sc, a3 * sc);
    uint2 o;
    o.x = *(unsigned*)&h01;
    o.y = *(unsigned*)&h23;
    *(uint2*)&g_Ye[(size_t)w * DF + 4 * lane] = o;
}

// ---------------- vertex gather + finalize: out[v] = relu(inv_sqrt_dv * sum Ye[e]) ----------------
__global__ __launch_bounds__(256) void k_vert(float* __restrict__ out) {
    int w    = (int)((blockIdx.x * 256u + threadIdx.x) >> 5);
    int lane = threadIdx.x & 31;
    if (w >= NN) return;
    int start = g_off[NE + w];
    int dv    = g_cnt[NE + w];

    float a0 = 0.f, a1 = 0.f, a2 = 0.f, a3 = 0.f;
    for (int base = 0; base < dv; base += 32) {
        int j   = base + lane;
        int idx = (j < dv) ? g_list[start + j] : 0;
        int m   = min(32, dv - base);
        #pragma unroll 4
        for (int t = 0; t < m; ++t) {
            int e = __shfl_sync(0xffffffffu, idx, t);
            uint2 u = __ldg((const uint2*)&g_Ye[(size_t)e * DF + 4 * lane]);
            float2 p = __half22float2(*(__half2*)&u.x);
            float2 q = __half22float2(*(__half2*)&u.y);
            a0 += p.x; a1 += p.y; a2 += q.x; a3 += q.y;
        }
    }
    float s = dv > 0 ? rsqrtf((float)dv) : 0.f;
    float4 o;
    o.x = fmaxf(a0 * s, 0.f);
    o.y = fmaxf(a1 * s, 0.f);
    o.z = fmaxf(a2 * s, 0.f);
    o.w = fmaxf(a3 * s, 0.f);
    *(float4*)&out[(size_t)w * DF + 4 * lane] = o;
}

// ---------------- launch ----------------
extern "C" void kernel_launch(void* const* d_in, const int* in_sizes, int n_in,
                              void* d_out, int out_size) {
    const float* X     = (const float*)d_in[0];
    const float* W     = (const float*)d_in[1];
    const float* b     = (const float*)d_in[2];
    const int*   v_idx = (const int*)d_in[3];
    const int*   e_idx = (const int*)d_in[4];
    float*       out   = (float*)d_out;
    int          nnz   = in_sizes[3];

    const int smem_gemm = (GR * DF + DF * DF) * (int)sizeof(float);  // 128 KB
    cudaFuncSetAttribute(k_gemm, cudaFuncAttributeMaxDynamicSharedMemorySize, smem_gemm);

    // Fork stream: GEMM depends only on degrees, overlaps scan+fill.
    cudaStream_t s2;
    cudaEvent_t  ev1, ev2;
    cudaStreamCreateWithFlags(&s2, cudaStreamNonBlocking);
    cudaEventCreateWithFlags(&ev1, cudaEventDisableTiming);
    cudaEventCreateWithFlags(&ev2, cudaEventDisableTiming);

    const int nScanBlocks = (NSEG + 1023) / 1024;   // 118

    k_zero<<<(NSEG + 255) / 256, 256>>>();
    k_degree<<<(nnz + 255) / 256, 256>>>(v_idx, e_idx, nnz);

    cudaEventRecord(ev1, 0);
    cudaStreamWaitEvent(s2, ev1, 0);
    k_gemm<<<(NN + GR - 1) / GR, GT, smem_gemm, s2>>>(X, W, b);
    cudaEventRecord(ev2, s2);

    k_scan1<<<nScanBlocks, 1024>>>(NSEG);
    k_scan2<<<1, 128>>>(nScanBlocks);
    k_scan3<<<nScanBlocks, 1024>>>(NSEG);
    k_fill<<<(nnz + 255) / 256, 256>>>(v_idx, e_idx, nnz);

    cudaStreamWaitEvent(0, ev2, 0);
    k_edge<<<(NE * 32 + 255) / 256, 256>>>();
    k_vert<<<(NN * 32 + 255) / 256, 256>>>(out);
    // NOTE: s2/ev1/ev2 intentionally not destroyed — destroying capture-joined
    // objects mid-capture can invalidate the graph; kernel_launch is called
    // only a handful of times (correctness + capture), so the host-side leak
    // is bounded and touches no device memory.
}